// round 2
// baseline (speedup 1.0000x reference)
#include <cuda_runtime.h>
#include <cuda_fp16.h>
#include <mma.h>

using namespace nvcuda;

#define BATCH 64
#define T_LEN 512
#define F_IN  132
#define F_PAD 192
#define HID   1024
#define G4    4096

// ---------------- device global scratch (no allocations allowed) ----------------
__device__ __half g_W5[5ULL * G4 * HID];              // Whh1, Wih2, Whh2, Wih3, Whh3 (fp16)
__device__ __half g_Wih1p[G4 * F_PAD];                // Wih1 padded 132->192
__device__ __half g_W1d[(size_t)G4 * HID];            // Wih1 @ Wd  (teacher-forcing fold)
__device__ __half g_Wdp[144 * HID];                   // Wd padded 132->144 rows
__device__ __half g_frames[(size_t)T_LEN * BATCH * F_PAD];
__device__ __half g_h2hist[(size_t)T_LEN * BATCH * HID];
__device__ __half g_h[2][3][BATCH][HID];              // ping-pong hidden states
__device__ float  g_c[3][BATCH][HID];                 // cell states (fp32, in-place)
__device__ float  g_b1f1[G4], g_b1f0[G4], g_b2[G4], g_b3[G4];

// ---------------- helpers ----------------
__device__ __forceinline__ void cp16(void* s, const void* g) {
    unsigned sa = (unsigned)__cvta_generic_to_shared(s);
    asm volatile("cp.async.cg.shared.global [%0], [%1], 16;\n" :: "r"(sa), "l"(g));
}
__device__ __forceinline__ void cp_commit() { asm volatile("cp.async.commit_group;\n"); }
__device__ __forceinline__ void cp_wait1()  { asm volatile("cp.async.wait_group 1;\n"); }
__device__ __forceinline__ void cp_wait0()  { asm volatile("cp.async.wait_group 0;\n"); }

// ---------------- setup kernels (run every launch: deterministic) ----------------
__global__ void k_conv5(const float* __restrict__ s0, const float* __restrict__ s1,
                        const float* __restrict__ s2, const float* __restrict__ s3,
                        const float* __restrict__ s4) {
    const size_t M = (size_t)G4 * HID;
    const float* srcs[5] = {s0, s1, s2, s3, s4};
    size_t n = 5 * M;
    for (size_t i = (size_t)blockIdx.x * blockDim.x + threadIdx.x; i < n;
         i += (size_t)gridDim.x * blockDim.x) {
        size_t m = i / M, r = i % M;
        g_W5[i] = __float2half_rn(srcs[m][r]);
    }
}

__global__ void k_padWih1(const float* __restrict__ Wih1) {
    size_t n = (size_t)G4 * F_PAD;
    for (size_t i = (size_t)blockIdx.x * blockDim.x + threadIdx.x; i < n;
         i += (size_t)gridDim.x * blockDim.x) {
        int c = (int)(i % F_PAD);
        int j = (int)(i / F_PAD);
        float v = (c < F_IN) ? Wih1[(size_t)j * F_IN + c] : 0.f;
        g_Wih1p[i] = __float2half_rn(v);
    }
}

__global__ void k_padWd(const float* __restrict__ Wd) {
    size_t n = (size_t)144 * HID;
    for (size_t i = (size_t)blockIdx.x * blockDim.x + threadIdx.x; i < n;
         i += (size_t)gridDim.x * blockDim.x) {
        int k = (int)(i % HID);
        int r = (int)(i / HID);
        float v = (r < F_IN) ? Wd[(size_t)r * HID + k] : 0.f;
        g_Wdp[i] = __float2half_rn(v);
    }
}

// W1d[j][k] = sum_f Wih1[j][f] * Wd[f][k]
__global__ void k_w1d(const float* __restrict__ Wih1, const float* __restrict__ Wd) {
    size_t gid = (size_t)blockIdx.x * blockDim.x + threadIdx.x;
    if (gid >= (size_t)G4 * HID) return;
    int j = (int)(gid >> 10), k = (int)(gid & 1023);
    float acc = 0.f;
    #pragma unroll 4
    for (int f = 0; f < F_IN; f++)
        acc += Wih1[(size_t)j * F_IN + f] * Wd[(size_t)f * HID + k];
    g_W1d[gid] = __float2half_rn(acc);
}

__global__ void k_bias(const float* __restrict__ bih1, const float* __restrict__ bhh1,
                       const float* __restrict__ bih2, const float* __restrict__ bhh2,
                       const float* __restrict__ bih3, const float* __restrict__ bhh3,
                       const float* __restrict__ Wih1, const float* __restrict__ bd) {
    int j = blockIdx.x * blockDim.x + threadIdx.x;
    if (j >= G4) return;
    float b1 = bih1[j] + bhh1[j];
    float acc = 0.f;
    for (int f = 0; f < F_IN; f++) acc += Wih1[(size_t)j * F_IN + f] * bd[f];
    g_b1f1[j] = b1;
    g_b1f0[j] = b1 + acc;
    g_b2[j] = bih2[j] + bhh2[j];
    g_b3[j] = bih3[j] + bhh3[j];
}

__global__ void k_frames(const float* __restrict__ rs) {
    size_t n = (size_t)T_LEN * BATCH * F_PAD;
    for (size_t i = (size_t)blockIdx.x * blockDim.x + threadIdx.x; i < n;
         i += (size_t)gridDim.x * blockDim.x) {
        int c = (int)(i % F_PAD);
        size_t rem = i / F_PAD;
        int b = (int)(rem % BATCH);
        int t = (int)(rem / BATCH);
        float v = (c < F_IN) ? rs[((size_t)b * T_LEN + t) * F_IN + c] : 0.f;
        g_frames[i] = __float2half_rn(v);
    }
}

__global__ void k_init() {
    size_t nh = 2ULL * 3 * BATCH * HID;
    size_t nc = 3ULL * BATCH * HID;
    __half* hp = &g_h[0][0][0][0];
    float*  cp = &g_c[0][0][0];
    for (size_t i = (size_t)blockIdx.x * blockDim.x + threadIdx.x; i < nh;
         i += (size_t)gridDim.x * blockDim.x) {
        hp[i] = __float2half_rn(0.f);
        if (i < nc) cp[i] = 0.f;
    }
}

// ---------------- per-timestep kernel ----------------
// 192 blocks: cell = bx/64, hidden tile of 16 -> 64 gate columns (i,f,g,o x16).
// Output tile 64 batch x 64 gatecols, fp16 WMMA with fp32 accum, fused LSTM elementwise.
struct Seg { const __half* a; int lda; const __half* w; int ldw; int nch; };

__global__ void __launch_bounds__(128) k_step(int t, int flag, int pin) {
    __shared__ __align__(16) unsigned char sraw[36864];
    __half (*As)[64][72] = reinterpret_cast<__half(*)[64][72]>(sraw);
    __half (*Ws)[64][72] = reinterpret_cast<__half(*)[64][72]>(sraw + 18432);
    float (*Gs)[68]      = reinterpret_cast<float(*)[68]>(sraw);

    int tid  = threadIdx.x;
    int warp = tid >> 5;
    int cell = blockIdx.x >> 6;
    int tile = blockIdx.x & 63;
    int h_base = tile << 4;

    const __half* hin = &g_h[pin][0][0][0];
    const __half* h0 = hin;
    const __half* h1 = hin + BATCH * HID;
    const __half* h2 = hin + 2 * BATCH * HID;

    const size_t M = (size_t)G4 * HID;
    Seg s0, s1;
    if (cell == 0) {
        if (flag) s0 = { g_frames + (size_t)t * BATCH * F_PAD, F_PAD, g_Wih1p, F_PAD, F_PAD / 64 };
        else      s0 = { h2, HID, g_W1d, HID, HID / 64 };
        s1 = { h0, HID, g_W5, HID, HID / 64 };
    } else if (cell == 1) {
        s0 = { h0, HID, g_W5 + 1 * M, HID, HID / 64 };
        s1 = { h1, HID, g_W5 + 2 * M, HID, HID / 64 };
    } else {
        s0 = { h1, HID, g_W5 + 3 * M, HID, HID / 64 };
        s1 = { h2, HID, g_W5 + 4 * M, HID, HID / 64 };
    }
    int nch = s0.nch + s1.nch;

    wmma::fragment<wmma::accumulator, 16, 16, 16, float> acc[4];
    #pragma unroll
    for (int c = 0; c < 4; c++) wmma::fill_fragment(acc[c], 0.f);

    auto load_chunk = [&](int i, int s) {
        const Seg& sg = (i < s0.nch) ? s0 : s1;
        int k0 = ((i < s0.nch) ? i : i - s0.nch) * 64;
        #pragma unroll
        for (int p = 0; p < 4; p++) {
            int idx = p * 128 + tid;
            int r = idx >> 3, c8 = idx & 7;
            cp16(&As[s][r][c8 * 8], sg.a + (size_t)r * sg.lda + k0 + c8 * 8);
            int grow = ((r >> 4) << 10) + h_base + (r & 15);
            cp16(&Ws[s][r][c8 * 8], sg.w + (size_t)grow * sg.ldw + k0 + c8 * 8);
        }
        cp_commit();
    };

    load_chunk(0, 0);
    for (int i = 0; i < nch; i++) {
        if (i + 1 < nch) { load_chunk(i + 1, (i + 1) & 1); cp_wait1(); }
        else             { cp_wait0(); }
        __syncthreads();
        int s = i & 1;
        #pragma unroll
        for (int kk = 0; kk < 4; kk++) {
            wmma::fragment<wmma::matrix_a, 16, 16, 16, __half, wmma::row_major> afr;
            wmma::load_matrix_sync(afr, &As[s][warp * 16][kk * 16], 72);
            #pragma unroll
            for (int c = 0; c < 4; c++) {
                wmma::fragment<wmma::matrix_b, 16, 16, 16, __half, wmma::col_major> bfr;
                wmma::load_matrix_sync(bfr, &Ws[s][c * 16][kk * 16], 72);
                wmma::mma_sync(acc[c], afr, bfr, acc[c]);
            }
        }
        __syncthreads();
    }

    #pragma unroll
    for (int c = 0; c < 4; c++)
        wmma::store_matrix_sync(&Gs[warp * 16][c * 16], acc[c], 68, wmma::mem_row_major);
    __syncthreads();

    const float* bias = (cell == 0) ? (flag ? g_b1f1 : g_b1f0) : (cell == 1 ? g_b2 : g_b3);
    __half* hout = &g_h[pin ^ 1][cell][0][0];
    float*  cst  = &g_c[cell][0][0];

    for (int idx = tid; idx < BATCH * 16; idx += 128) {
        int b = idx >> 4, jh = idx & 15;
        int hcol = h_base + jh;
        float gi = Gs[b][jh]      + bias[hcol];
        float gf = Gs[b][16 + jh] + bias[HID + hcol];
        float gg = Gs[b][32 + jh] + bias[2 * HID + hcol];
        float go = Gs[b][48 + jh] + bias[3 * HID + hcol];
        float si = 1.f / (1.f + expf(-gi));
        float sf = 1.f / (1.f + expf(-gf));
        float so = 1.f / (1.f + expf(-go));
        float tg = tanhf(gg);
        float cold = cst[b * HID + hcol];
        float cn = sf * cold + si * tg;
        float hn = so * tanhf(cn);
        cst[b * HID + hcol] = cn;
        __half hh = __float2half_rn(hn);
        hout[b * HID + hcol] = hh;
        if (cell == 2)
            g_h2hist[(size_t)t * BATCH * HID + (size_t)b * HID + hcol] = hh;
    }
}

// ---------------- final batched output GEMM: out = h2hist @ Wd^T + bd ----------------
__global__ void __launch_bounds__(128) k_out(const float* __restrict__ bd,
                                             float* __restrict__ out) {
    __shared__ __align__(16) unsigned char sraw[32256];
    __half (*As)[64][72] = reinterpret_cast<__half(*)[64][72]>(sraw);
    __half (*Ws)[48][72] = reinterpret_cast<__half(*)[48][72]>(sraw + 18432);
    float (*Gs)[52]      = reinterpret_cast<float(*)[52]>(sraw);

    int tid = threadIdx.x, warp = tid >> 5;
    int r0 = blockIdx.x * 64;   // row block over T*B = 32768
    int f0 = blockIdx.y * 48;   // col block over 144 padded output features

    const __half* A = g_h2hist + (size_t)r0 * HID;

    wmma::fragment<wmma::accumulator, 16, 16, 16, float> acc[3];
    #pragma unroll
    for (int c = 0; c < 3; c++) wmma::fill_fragment(acc[c], 0.f);

    auto load_chunk = [&](int i, int s) {
        int k0 = i * 64;
        #pragma unroll
        for (int p = 0; p < 4; p++) {
            int idx = p * 128 + tid;
            int r = idx >> 3, c8 = idx & 7;
            cp16(&As[s][r][c8 * 8], A + (size_t)r * HID + k0 + c8 * 8);
        }
        #pragma unroll
        for (int p = 0; p < 3; p++) {
            int idx = p * 128 + tid;
            int r = idx >> 3, c8 = idx & 7;
            cp16(&Ws[s][r][c8 * 8], g_Wdp + (size_t)(f0 + r) * HID + k0 + c8 * 8);
        }
        cp_commit();
    };

    const int nch = HID / 64;
    load_chunk(0, 0);
    for (int i = 0; i < nch; i++) {
        if (i + 1 < nch) { load_chunk(i + 1, (i + 1) & 1); cp_wait1(); }
        else             { cp_wait0(); }
        __syncthreads();
        int s = i & 1;
        #pragma unroll
        for (int kk = 0; kk < 4; kk++) {
            wmma::fragment<wmma::matrix_a, 16, 16, 16, __half, wmma::row_major> afr;
            wmma::load_matrix_sync(afr, &As[s][warp * 16][kk * 16], 72);
            #pragma unroll
            for (int c = 0; c < 3; c++) {
                wmma::fragment<wmma::matrix_b, 16, 16, 16, __half, wmma::col_major> bfr;
                wmma::load_matrix_sync(bfr, &Ws[s][c * 16][kk * 16], 72);
                wmma::mma_sync(acc[c], afr, bfr, acc[c]);
            }
        }
        __syncthreads();
    }

    #pragma unroll
    for (int c = 0; c < 3; c++)
        wmma::store_matrix_sync(&Gs[warp * 16][c * 16], acc[c], 52, wmma::mem_row_major);
    __syncthreads();

    for (int idx = tid; idx < 64 * 48; idx += 128) {
        int rr = idx / 48, cc = idx % 48;
        int f = f0 + cc;
        if (f >= F_IN) continue;
        int r = r0 + rr;
        int tt = r >> 6, b = r & 63;
        out[(size_t)b * (T_LEN * F_IN) + (size_t)tt * F_IN + f] = Gs[rr][cc] + bd[f];
    }
}

// ---------------- launch ----------------
extern "C" void kernel_launch(void* const* d_in, const int* in_sizes, int n_in,
                              void* d_out, int out_size) {
    (void)in_sizes; (void)n_in; (void)out_size;
    const float* real_seq = (const float*)d_in[0];
    const float* Wih1 = (const float*)d_in[1];
    const float* Whh1 = (const float*)d_in[2];
    const float* bih1 = (const float*)d_in[3];
    const float* bhh1 = (const float*)d_in[4];
    const float* Wih2 = (const float*)d_in[5];
    const float* Whh2 = (const float*)d_in[6];
    const float* bih2 = (const float*)d_in[7];
    const float* bhh2 = (const float*)d_in[8];
    const float* Wih3 = (const float*)d_in[9];
    const float* Whh3 = (const float*)d_in[10];
    const float* bih3 = (const float*)d_in[11];
    const float* bhh3 = (const float*)d_in[12];
    const float* Wd   = (const float*)d_in[13];
    const float* bd   = (const float*)d_in[14];
    float* out = (float*)d_out;

    // setup (rebuilt every launch for determinism)
    k_conv5<<<8192, 256>>>(Whh1, Wih2, Whh2, Wih3, Whh3);
    k_padWih1<<<1024, 256>>>(Wih1);
    k_padWd<<<288, 256>>>(Wd);
    k_w1d<<<(G4 * HID) / 256, 256>>>(Wih1, Wd);
    k_bias<<<16, 256>>>(bih1, bhh1, bih2, bhh2, bih3, bhh3, Wih1, bd);
    k_frames<<<4096, 256>>>(real_seq);
    k_init<<<1536, 256>>>();

    // recurrence
    for (int t = 0; t < T_LEN; t++) {
        int flag = ((t % 10) < 5) ? 1 : 0;
        k_step<<<192, 128>>>(t, flag, t & 1);
    }

    // batched output projection
    dim3 og((T_LEN * BATCH) / 64, 3);
    k_out<<<og, 128>>>(bd, out);
}